// round 15
// baseline (speedup 1.0000x reference)
#include <cuda_runtime.h>
#include <math.h>
#include <stdint.h>

#define NB 128
#define NJ 32
#define NI 1152
#define NN 16
#define TI 64
#define NTILES 18

// ---------- global scratch ----------
__device__ float    g_V0[NB * NJ * NN];
__device__ float    g_V1[NB * NJ * NN];
__device__ float    g_VW[NB * NJ * NN];                // v0 + v1
__device__ float    g_S_part[NTILES * NB * NJ * NN];
__device__ float    g_sc_part[NTILES * NB * NJ];
__device__ float    g_ent_part[2 * NTILES * NB];
__device__ unsigned g_mask1[NB];
__device__ unsigned g_mask2[NB];

#define CP_ASYNC16(sa, gp) \
    asm volatile("cp.async.cg.shared.global [%0], [%1], 16;\n" :: "r"(sa), "l"(gp) : "memory")
#define CP_COMMIT() asm volatile("cp.async.commit_group;\n" ::: "memory")
#define CP_WAIT2()  asm volatile("cp.async.wait_group 2;\n" ::: "memory")

// =====================================================================
// Pass 1: s0 = (1/32)*sum_i u ; v0 = squash(s0 + bias)
// =====================================================================
__global__ void __launch_bounds__(256) pass1_kernel(const float* __restrict__ u,
                                                    const float* __restrict__ bias) {
    __shared__ float sred[64 * 17];
    int j = blockIdx.x, b = blockIdx.y;
    int t = threadIdx.x;
    int q = t & 3, ir = t >> 2;
    const float* base = u + (size_t)(b * NJ + j) * (NI * NN);
    float4 acc = make_float4(0.f, 0.f, 0.f, 0.f);
#pragma unroll
    for (int k = 0; k < 18; ++k) {
        int i = ir + k * 64;
        float4 v = *reinterpret_cast<const float4*>(base + (size_t)i * NN + q * 4);
        acc.x += v.x; acc.y += v.y; acc.z += v.z; acc.w += v.w;
    }
    float* sp = sred + ir * 17 + q * 4;
    sp[0] = acc.x; sp[1] = acc.y; sp[2] = acc.z; sp[3] = acc.w;
    __syncthreads();
    if (t < 16) {
        int n = t;
        float s = 0.f;
        for (int r = 0; r < 64; ++r) s += sred[r * 17 + n];
        s *= (1.f / 32.f);
        float ss = s;
#pragma unroll
        for (int o = 8; o; o >>= 1) ss += __shfl_xor_sync(0xFFFFu, ss, o);
        float tb = (ss == 0.f) ? 0.f : (s + bias[j * NN + n]);
        float sq = tb * tb;
#pragma unroll
        for (int o = 8; o; o >>= 1) sq += __shfl_xor_sync(0xFFFFu, sq, o);
        float v = (sq / (1.f + sq)) * tb / sqrtf(sq + 1e-8f);
        g_V0[(b * NJ + j) * NN + n] = v;
    }
}

// =====================================================================
// SCORE sweep (R13 config): 3-stage cp.async pipeline, 1 row per step,
// 4 CTAs/SM, static smem (<=24KB).
// =====================================================================
template <int KSEL>
__global__ void __launch_bounds__(256, 4) score_kernel(const float* __restrict__ u,
                                                       const float* __restrict__ vglob,
                                                       const unsigned* __restrict__ maskp) {
    constexpr int ITER = (KSEL + 7) / 8;
    __shared__ float4 pipe[3][8][ITER][32];
    __shared__ int   sj[32];
    __shared__ float ssum[8][32];

    int t = threadIdx.x, lane = t & 31, w = t >> 5;
    int tb = blockIdx.x, b = blockIdx.y, i0 = tb * TI;
    int q = lane & 3, s = lane >> 2;
    unsigned msk = maskp ? maskp[b] : 0xFFFFFFFFu;
    if (t < 32 && ((msk >> t) & 1u))
        sj[__popc(msk & ((1u << t) - 1u))] = t;
    __syncthreads();

    const float* ub = u + (size_t)b * (NJ * NI * NN);
    bool  val[ITER];
    int   off[ITER];
    float4 vj[ITER];
#pragma unroll
    for (int it = 0; it < ITER; ++it) {
        int idx = it * 8 + s;
        val[it] = (idx < KSEL);
        int j = sj[val[it] ? idx : 0];
        off[it] = j * (NI * NN) + q * 4;
        vj[it] = *reinterpret_cast<const float4*>(vglob + (b * NJ + j) * NN + q * 4);
        if (!val[it]) {
#pragma unroll
            for (int st = 0; st < 3; ++st)
                pipe[st][w][it][lane] = make_float4(0.f, 0.f, 0.f, 0.f);
        }
    }

    float sc[ITER];
#pragma unroll
    for (int it = 0; it < ITER; ++it) sc[it] = 0.f;

#pragma unroll
    for (int p = 0; p < 2; ++p) {
        int i = i0 + w * 8 + p;
#pragma unroll
        for (int it = 0; it < ITER; ++it) {
            if (val[it]) {
                unsigned sa = (unsigned)__cvta_generic_to_shared(&pipe[p][w][it][lane]);
                CP_ASYNC16(sa, ub + off[it] + i * NN);
            }
        }
        CP_COMMIT();
    }

#pragma unroll
    for (int r = 0; r < 8; ++r) {
        if (r < 6) {
            int i = i0 + w * 8 + r + 2;
            int st = (r + 2) % 3;
#pragma unroll
            for (int it = 0; it < ITER; ++it) {
                if (val[it]) {
                    unsigned sa = (unsigned)__cvta_generic_to_shared(&pipe[st][w][it][lane]);
                    CP_ASYNC16(sa, ub + off[it] + i * NN);
                }
            }
            CP_COMMIT();
        } else {
            CP_COMMIT();
        }
        CP_WAIT2();

        int st = r % 3;
        float4 uu[ITER];
#pragma unroll
        for (int it = 0; it < ITER; ++it) uu[it] = pipe[st][w][it][lane];

        float e[ITER];
        float S = 0.f;
#pragma unroll
        for (int it = 0; it < ITER; ++it) {
            float dd = uu[it].x * vj[it].x + uu[it].y * vj[it].y
                     + uu[it].z * vj[it].z + uu[it].w * vj[it].w;
            dd += __shfl_xor_sync(0xFFFFFFFFu, dd, 1);
            dd += __shfl_xor_sync(0xFFFFFFFFu, dd, 2);
            e[it] = val[it] ? __expf(dd) : 0.f;
            S += e[it];
        }
        S += __shfl_xor_sync(0xFFFFFFFFu, S, 4);
        S += __shfl_xor_sync(0xFFFFFFFFu, S, 8);
        S += __shfl_xor_sync(0xFFFFFFFFu, S, 16);
        float inv = __fdividef(1.f, S);
#pragma unroll
        for (int it = 0; it < ITER; ++it) sc[it] += e[it] * inv;
    }

    if (q == 0) {
#pragma unroll
        for (int it = 0; it < ITER; ++it)
            if (val[it]) ssum[w][it * 8 + s] = sc[it];
    }
    __syncthreads();
    if (t < 32) {
        bool selj = (msk >> t) & 1u;
        float v = 0.f;
        if (selj) {
            int idx = __popc(msk & ((1u << t) - 1u));
#pragma unroll
            for (int ww = 0; ww < 8; ++ww) v += ssum[ww][idx];
        }
        g_sc_part[tb * (NB * NJ) + b * NJ + t] = v;
    }
}

// =====================================================================
// SUM sweep: row-PAIR processing for 2x chain ILP. 3-stage pipe of
// 2-row stages in DYNAMIC smem (72KB for KSEL=20), 3 CTAs/SM.
// ssum aliased over the dead pipe at the tail (sync guards).
// =====================================================================
template <int KSEL>
__global__ void __launch_bounds__(256, 3) sum_kernel(const float* __restrict__ u,
                                                     const float* __restrict__ vglob,
                                                     const unsigned* __restrict__ maskp,
                                                     int ent_slot) {
    constexpr int ITER = (KSEL + 7) / 8;
    constexpr int SWORDS = KSEL * 16;
    extern __shared__ __align__(16) char smbuf[];
    __shared__ int   sj[32];
    __shared__ float red[8];

    typedef float4 PipeT[3][8][ITER][2][32];
    PipeT& pipe = *reinterpret_cast<PipeT*>(smbuf);
    typedef float SsumT[8][SWORDS];
    SsumT& ssum = *reinterpret_cast<SsumT*>(smbuf);

    int t = threadIdx.x, lane = t & 31, w = t >> 5;
    int tb = blockIdx.x, b = blockIdx.y, i0 = tb * TI;
    int q = lane & 3, s = lane >> 2;
    unsigned msk = maskp[b];
    if (t < 32 && ((msk >> t) & 1u))
        sj[__popc(msk & ((1u << t) - 1u))] = t;
    __syncthreads();

    const float* ub = u + (size_t)b * (NJ * NI * NN);
    bool  val[ITER];
    int   off[ITER];
    float4 vj[ITER];
#pragma unroll
    for (int it = 0; it < ITER; ++it) {
        int idx = it * 8 + s;
        val[it] = (idx < KSEL);
        int j = sj[val[it] ? idx : 0];
        off[it] = j * (NI * NN) + q * 4;
        vj[it] = *reinterpret_cast<const float4*>(vglob + (b * NJ + j) * NN + q * 4);
        if (!val[it]) {
#pragma unroll
            for (int st = 0; st < 3; ++st) {
                pipe[st][w][it][0][lane] = make_float4(0.f, 0.f, 0.f, 0.f);
                pipe[st][w][it][1][lane] = make_float4(0.f, 0.f, 0.f, 0.f);
            }
        }
    }

    float4 acc[ITER];
#pragma unroll
    for (int it = 0; it < ITER; ++it) acc[it] = make_float4(0.f, 0.f, 0.f, 0.f);
    float entlog = 0.f;
    float cdacc  = 0.f;

    // prologue: pairs 0,1
#pragma unroll
    for (int p = 0; p < 2; ++p) {
#pragma unroll
        for (int rr = 0; rr < 2; ++rr) {
            int i = i0 + w * 8 + p * 2 + rr;
#pragma unroll
            for (int it = 0; it < ITER; ++it) {
                if (val[it]) {
                    unsigned sa = (unsigned)__cvta_generic_to_shared(&pipe[p][w][it][rr][lane]);
                    CP_ASYNC16(sa, ub + off[it] + i * NN);
                }
            }
        }
        CP_COMMIT();
    }

#pragma unroll
    for (int p = 0; p < 4; ++p) {
        if (p < 2) {
            int st = (p + 2) % 3;
#pragma unroll
            for (int rr = 0; rr < 2; ++rr) {
                int i = i0 + w * 8 + (p + 2) * 2 + rr;
#pragma unroll
                for (int it = 0; it < ITER; ++it) {
                    if (val[it]) {
                        unsigned sa = (unsigned)__cvta_generic_to_shared(&pipe[st][w][it][rr][lane]);
                        CP_ASYNC16(sa, ub + off[it] + i * NN);
                    }
                }
            }
            CP_COMMIT();
        } else {
            CP_COMMIT();
        }
        CP_WAIT2();   // pair p complete

        int st = p % 3;
        float4 ua[ITER], ubr[ITER];
#pragma unroll
        for (int it = 0; it < ITER; ++it) {
            ua[it]  = pipe[st][w][it][0][lane];
            ubr[it] = pipe[st][w][it][1][lane];
        }

        // two independent softmax chains, interleaved
        float eA[ITER], eB[ITER];
        float SA = 0.f, SB = 0.f, CDA = 0.f, CDB = 0.f;
#pragma unroll
        for (int it = 0; it < ITER; ++it) {
            float dA = ua[it].x * vj[it].x + ua[it].y * vj[it].y
                     + ua[it].z * vj[it].z + ua[it].w * vj[it].w;
            float dB = ubr[it].x * vj[it].x + ubr[it].y * vj[it].y
                     + ubr[it].z * vj[it].z + ubr[it].w * vj[it].w;
            dA += __shfl_xor_sync(0xFFFFFFFFu, dA, 1);
            dB += __shfl_xor_sync(0xFFFFFFFFu, dB, 1);
            dA += __shfl_xor_sync(0xFFFFFFFFu, dA, 2);
            dB += __shfl_xor_sync(0xFFFFFFFFu, dB, 2);
            eA[it] = val[it] ? __expf(dA) : 0.f;
            eB[it] = val[it] ? __expf(dB) : 0.f;
            SA += eA[it];
            SB += eB[it];
            if (val[it]) { CDA += eA[it] * dA; CDB += eB[it] * dB; }
        }
        SA += __shfl_xor_sync(0xFFFFFFFFu, SA, 4);
        SB += __shfl_xor_sync(0xFFFFFFFFu, SB, 4);
        SA += __shfl_xor_sync(0xFFFFFFFFu, SA, 8);
        SB += __shfl_xor_sync(0xFFFFFFFFu, SB, 8);
        SA += __shfl_xor_sync(0xFFFFFFFFu, SA, 16);
        SB += __shfl_xor_sync(0xFFFFFFFFu, SB, 16);
        float invA = __fdividef(1.f, SA);
        float invB = __fdividef(1.f, SB);
        entlog += __logf(SA) + __logf(SB);
        cdacc  += CDA * invA + CDB * invB;
#pragma unroll
        for (int it = 0; it < ITER; ++it) {
            float cA = eA[it] * invA;
            float cB = eB[it] * invB;
            acc[it].x += cA * ua[it].x + cB * ubr[it].x;
            acc[it].y += cA * ua[it].y + cB * ubr[it].y;
            acc[it].z += cA * ua[it].z + cB * ubr[it].z;
            acc[it].w += cA * ua[it].w + cB * ubr[it].w;
        }
    }

    // finish entropy
    cdacc += __shfl_xor_sync(0xFFFFFFFFu, cdacc, 4);
    cdacc += __shfl_xor_sync(0xFFFFFFFFu, cdacc, 8);
    cdacc += __shfl_xor_sync(0xFFFFFFFFu, cdacc, 16);
    float ent = entlog - cdacc;
    if (lane == 0) red[w] = ent;

    // ssum aliases pipe: block sync before overwrite
    __syncthreads();
#pragma unroll
    for (int it = 0; it < ITER; ++it) {
        if (val[it]) {
            int base = (it * 8 + s) * 16 + q * 4;
            *reinterpret_cast<float4*>(&ssum[w][base]) = acc[it];
        }
    }
    __syncthreads();
    for (int k = t; k < KSEL * 16; k += 256) {
        float v = 0.f;
#pragma unroll
        for (int ww = 0; ww < 8; ++ww) v += ssum[ww][k];
        int idx = k >> 4, n = k & 15;
        int j = sj[idx];
        g_S_part[(size_t)tb * (NB * NJ * NN) + (size_t)(b * NJ + j) * NN + n] = v;
    }
    if (t == 0) {
        float e = 0.f;
#pragma unroll
        for (int x = 0; x < 8; ++x) e += red[x];
        g_ent_part[ent_slot * (NTILES * NB) + tb * NB + b] = e;
    }
}

// =====================================================================
// top-k per example (tie-break: lower index wins)
// =====================================================================
__global__ void topk_kernel(int K, int which) {
    int b = blockIdx.x, j = threadIdx.x;
    float sc = 0.f;
#pragma unroll
    for (int tt = 0; tt < NTILES; ++tt) sc += g_sc_part[tt * (NB * NJ) + b * NJ + j];
    int rank = 0;
#pragma unroll
    for (int k = 0; k < 32; ++k) {
        float o = __shfl_sync(0xFFFFFFFFu, sc, k);
        rank += (o > sc) || (o == sc && k < j);
    }
    unsigned m = __ballot_sync(0xFFFFFFFFu, rank < K);
    if (j == 0) {
        if (which == 1) g_mask1[b] = m; else g_mask2[b] = m;
    }
}

// =====================================================================
// squash from s partials (mask-aware; unselected capsules -> v = 0)
// =====================================================================
__device__ __forceinline__ float squash_elem(int gid, bool sel, const float* __restrict__ bias) {
    float s = 0.f;
    if (sel) {
#pragma unroll
        for (int tt = 0; tt < NTILES; ++tt) s += g_S_part[(size_t)tt * (NB * NJ * NN) + gid];
    }
    float ss = s;
#pragma unroll
    for (int o = 8; o; o >>= 1) ss += __shfl_xor_sync(0xFFFFFFFFu, ss, o);
    int n = gid & 15, j = (gid >> 4) & 31;
    float tb = (ss == 0.f) ? 0.f : (s + bias[j * NN + n]);
    float sq = tb * tb;
#pragma unroll
    for (int o = 8; o; o >>= 1) sq += __shfl_xor_sync(0xFFFFFFFFu, sq, o);
    return (sq == 0.f) ? 0.f : (sq / (1.f + sq)) * tb / sqrtf(sq + 1e-8f);
}

__global__ void __launch_bounds__(256) squash_mid_kernel(const float* __restrict__ bias) {
    int gid = blockIdx.x * 256 + threadIdx.x;
    int j = (gid >> 4) & 31, b = gid >> 9;
    bool sel = (g_mask1[b] >> j) & 1u;
    float v = squash_elem(gid, sel, bias);
    g_V1[gid] = v;
    g_VW[gid] = g_V0[gid] + v;
}

__global__ void __launch_bounds__(256) final_kernel(const float* __restrict__ bias,
                                                    float* __restrict__ out, int out_size) {
    int gid = blockIdx.x * 256 + threadIdx.x;
    int j = (gid >> 4) & 31, b = gid >> 9;
    bool sel = (g_mask2[b] >> j) & 1u;
    out[gid] = squash_elem(gid, sel, bias);
    if (blockIdx.x == 0 && threadIdx.x < NB && out_size >= NB * NJ * NN + NB * 3) {
        int bb = threadIdx.x;
        float e1 = 0.f, e2 = 0.f;
        for (int tt = 0; tt < NTILES; ++tt) {
            e1 += g_ent_part[0 * (NTILES * NB) + tt * NB + bb];
            e2 += g_ent_part[1 * (NTILES * NB) + tt * NB + bb];
        }
        float* eo = out + NB * NJ * NN;
        eo[bb * 3 + 0] = logf(32.0f);
        eo[bb * 3 + 1] = e1 * (1.f / (float)NI);
        eo[bb * 3 + 2] = e2 * (1.f / (float)NI);
    }
}

// =====================================================================
extern "C" void kernel_launch(void* const* d_in, const int* in_sizes, int n_in,
                              void* d_out, int out_size) {
    const float* u    = (const float*)d_in[0];
    const float* bias = (const float*)d_in[1];
    float* out        = (float*)d_out;

    float *v0p, *vwp;
    unsigned *m1p, *m2p;
    cudaGetSymbolAddress((void**)&v0p, g_V0);
    cudaGetSymbolAddress((void**)&vwp, g_VW);
    cudaGetSymbolAddress((void**)&m1p, g_mask1);
    cudaGetSymbolAddress((void**)&m2p, g_mask2);

    // dynamic smem sizes for the row-pair sum kernels
    const int smem20 = 3 * 8 * 3 * 2 * 32 * 16;   // 73728 B
    const int smem12 = 3 * 8 * 2 * 2 * 32 * 16;   // 49152 B
    cudaFuncSetAttribute(sum_kernel<20>, cudaFuncAttributeMaxDynamicSharedMemorySize, smem20);
    cudaFuncSetAttribute(sum_kernel<12>, cudaFuncAttributeMaxDynamicSharedMemorySize, smem12);

    dim3 sgrid(NTILES, NB);

    // sweep 1 (302 MB): s0 -> v0
    pass1_kernel<<<dim3(NJ, NB), 256>>>(u, bias);
    // sweep 2 (302 MB): scores of softmax(u·v0) -> top-20 -> mask1
    score_kernel<32><<<sgrid, 256>>>(u, v0p, nullptr);
    topk_kernel<<<NB, 32>>>(20, 1);
    // sweep 3 (189 MB): c1, entropy1, s1 -> v1, w = v0 + v1
    sum_kernel<20><<<sgrid, 256, smem20>>>(u, v0p, m1p, 0);
    squash_mid_kernel<<<256, 256>>>(bias);
    // sweep 4 (189 MB): scores of softmax(u·w, mask1) -> top-12 -> mask2
    score_kernel<20><<<sgrid, 256>>>(u, vwp, m1p);
    topk_kernel<<<NB, 32>>>(12, 2);
    // sweep 5 (113 MB): c2, entropy2, s2 -> v2 (out)
    sum_kernel<12><<<sgrid, 256, smem12>>>(u, vwp, m2p, 1);
    final_kernel<<<256, 256>>>(bias, out, out_size);
}

// round 16
// speedup vs baseline: 1.0445x; 1.0445x over previous
#include <cuda_runtime.h>
#include <math.h>
#include <stdint.h>

#define NB 128
#define NJ 32
#define NI 1152
#define NN 16
#define TI 128
#define NTILES 9

// ---------- global scratch ----------
__device__ float    g_V0[NB * NJ * NN];
__device__ float    g_V1[NB * NJ * NN];
__device__ float    g_VW[NB * NJ * NN];                // v0 + v1
__device__ float    g_S_part[NTILES * NB * NJ * NN];
__device__ float    g_sc_part[NTILES * NB * NJ];
__device__ float    g_ent_part[2 * NTILES * NB];
__device__ unsigned g_mask1[NB];
__device__ unsigned g_mask2[NB];

#define CP_ASYNC16(sa, gp) \
    asm volatile("cp.async.cg.shared.global [%0], [%1], 16;\n" :: "r"(sa), "l"(gp) : "memory")
#define CP_COMMIT() asm volatile("cp.async.commit_group;\n" ::: "memory")
#define CP_WAIT2()  asm volatile("cp.async.wait_group 2;\n" ::: "memory")

// =====================================================================
// Pass 1: s0 = (1/32)*sum_i u ; v0 = squash(s0 + bias)
// =====================================================================
__global__ void __launch_bounds__(256) pass1_kernel(const float* __restrict__ u,
                                                    const float* __restrict__ bias) {
    __shared__ float sred[64 * 17];
    int j = blockIdx.x, b = blockIdx.y;
    int t = threadIdx.x;
    int q = t & 3, ir = t >> 2;
    const float* base = u + (size_t)(b * NJ + j) * (NI * NN);
    float4 acc = make_float4(0.f, 0.f, 0.f, 0.f);
#pragma unroll
    for (int k = 0; k < 18; ++k) {
        int i = ir + k * 64;
        float4 v = *reinterpret_cast<const float4*>(base + (size_t)i * NN + q * 4);
        acc.x += v.x; acc.y += v.y; acc.z += v.z; acc.w += v.w;
    }
    float* sp = sred + ir * 17 + q * 4;
    sp[0] = acc.x; sp[1] = acc.y; sp[2] = acc.z; sp[3] = acc.w;
    __syncthreads();
    if (t < 16) {
        int n = t;
        float s = 0.f;
        for (int r = 0; r < 64; ++r) s += sred[r * 17 + n];
        s *= (1.f / 32.f);
        float ss = s;
#pragma unroll
        for (int o = 8; o; o >>= 1) ss += __shfl_xor_sync(0xFFFFu, ss, o);
        float tb = (ss == 0.f) ? 0.f : (s + bias[j * NN + n]);
        float sq = tb * tb;
#pragma unroll
        for (int o = 8; o; o >>= 1) sq += __shfl_xor_sync(0xFFFFu, sq, o);
        float v = (sq / (1.f + sq)) * tb / sqrtf(sq + 1e-8f);
        g_V0[(b * NJ + j) * NN + n] = v;
    }
}

// =====================================================================
// SCORE sweep: 3-stage cp.async pipeline, 1 row/step, 16 rows/warp,
// 4 CTAs/SM. Writes per-tile node-score partials.
// =====================================================================
template <int KSEL>
__global__ void __launch_bounds__(256, 4) score_kernel(const float* __restrict__ u,
                                                       const float* __restrict__ vglob,
                                                       const unsigned* __restrict__ maskp) {
    constexpr int ITER = (KSEL + 7) / 8;
    __shared__ float4 pipe[3][8][ITER][32];
    __shared__ int   sj[32];
    __shared__ float ssum[8][32];

    int t = threadIdx.x, lane = t & 31, w = t >> 5;
    int tb = blockIdx.x, b = blockIdx.y, i0 = tb * TI;
    int q = lane & 3, s = lane >> 2;
    unsigned msk = maskp ? maskp[b] : 0xFFFFFFFFu;
    if (t < 32 && ((msk >> t) & 1u))
        sj[__popc(msk & ((1u << t) - 1u))] = t;
    __syncthreads();

    const float* ub = u + (size_t)b * (NJ * NI * NN);
    bool  val[ITER];
    int   off[ITER];
    float4 vj[ITER];
#pragma unroll
    for (int it = 0; it < ITER; ++it) {
        int idx = it * 8 + s;
        val[it] = (idx < KSEL);
        int j = sj[val[it] ? idx : 0];
        off[it] = j * (NI * NN) + q * 4;
        vj[it] = *reinterpret_cast<const float4*>(vglob + (b * NJ + j) * NN + q * 4);
        if (!val[it]) {
#pragma unroll
            for (int st = 0; st < 3; ++st)
                pipe[st][w][it][lane] = make_float4(0.f, 0.f, 0.f, 0.f);
        }
    }

    float sc[ITER];
#pragma unroll
    for (int it = 0; it < ITER; ++it) sc[it] = 0.f;

#pragma unroll
    for (int p = 0; p < 2; ++p) {
        int i = i0 + w * 16 + p;
#pragma unroll
        for (int it = 0; it < ITER; ++it) {
            if (val[it]) {
                unsigned sa = (unsigned)__cvta_generic_to_shared(&pipe[p][w][it][lane]);
                CP_ASYNC16(sa, ub + off[it] + i * NN);
            }
        }
        CP_COMMIT();
    }

#pragma unroll
    for (int r = 0; r < 16; ++r) {
        if (r < 14) {
            int i = i0 + w * 16 + r + 2;
            int st = (r + 2) % 3;
#pragma unroll
            for (int it = 0; it < ITER; ++it) {
                if (val[it]) {
                    unsigned sa = (unsigned)__cvta_generic_to_shared(&pipe[st][w][it][lane]);
                    CP_ASYNC16(sa, ub + off[it] + i * NN);
                }
            }
            CP_COMMIT();
        } else {
            CP_COMMIT();
        }
        CP_WAIT2();

        int st = r % 3;
        float4 uu[ITER];
#pragma unroll
        for (int it = 0; it < ITER; ++it) uu[it] = pipe[st][w][it][lane];

        float e[ITER];
        float S = 0.f;
#pragma unroll
        for (int it = 0; it < ITER; ++it) {
            float dd = uu[it].x * vj[it].x + uu[it].y * vj[it].y
                     + uu[it].z * vj[it].z + uu[it].w * vj[it].w;
            dd += __shfl_xor_sync(0xFFFFFFFFu, dd, 1);
            dd += __shfl_xor_sync(0xFFFFFFFFu, dd, 2);
            e[it] = val[it] ? __expf(dd) : 0.f;
            S += e[it];
        }
        S += __shfl_xor_sync(0xFFFFFFFFu, S, 4);
        S += __shfl_xor_sync(0xFFFFFFFFu, S, 8);
        S += __shfl_xor_sync(0xFFFFFFFFu, S, 16);
        float inv = __fdividef(1.f, S);
#pragma unroll
        for (int it = 0; it < ITER; ++it) sc[it] += e[it] * inv;
    }

    if (q == 0) {
#pragma unroll
        for (int it = 0; it < ITER; ++it)
            if (val[it]) ssum[w][it * 8 + s] = sc[it];
    }
    __syncthreads();
    if (t < 32) {
        bool selj = (msk >> t) & 1u;
        float v = 0.f;
        if (selj) {
            int idx = __popc(msk & ((1u << t) - 1u));
#pragma unroll
            for (int ww = 0; ww < 8; ++ww) v += ssum[ww][idx];
        }
        g_sc_part[tb * (NB * NJ) + b * NJ + t] = v;
    }
}

// =====================================================================
// SUM sweep: computes its own top-KSEL mask from g_sc_part (replaces
// the separate topk kernel; block tb==0 persists the mask), then the
// R13 1-row 3-stage pipeline: dots -> shift-free softmax (+entropy)
// -> register-held c*u accumulation. 4 CTAs/SM.
// =====================================================================
template <int KSEL>
__global__ void __launch_bounds__(256, 4) sum_kernel(const float* __restrict__ u,
                                                     const float* __restrict__ vglob,
                                                     unsigned* __restrict__ mask_out,
                                                     int ent_slot) {
    constexpr int ITER = (KSEL + 7) / 8;
    constexpr int SWORDS = KSEL * 16;
    __shared__ float4 pipe[3][8][ITER][32];
    __shared__ int   sj[32];
    __shared__ float red[8];
    __shared__ float ssum[8][SWORDS];
    __shared__ unsigned smsk;

    int t = threadIdx.x, lane = t & 31, w = t >> 5;
    int tb = blockIdx.x, b = blockIdx.y, i0 = tb * TI;
    int q = lane & 3, s = lane >> 2;

    // top-KSEL mask from node-score partials (deterministic, matches topk)
    if (w == 0) {
        float scv = 0.f;
#pragma unroll
        for (int tt = 0; tt < NTILES; ++tt)
            scv += g_sc_part[tt * (NB * NJ) + b * NJ + lane];
        int rank = 0;
#pragma unroll
        for (int k = 0; k < 32; ++k) {
            float o = __shfl_sync(0xFFFFFFFFu, scv, k);
            rank += (o > scv) || (o == scv && k < lane);
        }
        unsigned m = __ballot_sync(0xFFFFFFFFu, rank < KSEL);
        if (lane == 0) {
            smsk = m;
            if (tb == 0) mask_out[b] = m;
        }
        if ((m >> lane) & 1u)
            sj[__popc(m & ((1u << lane) - 1u))] = lane;
    }
    __syncthreads();
    unsigned msk = smsk;

    const float* ub = u + (size_t)b * (NJ * NI * NN);
    bool  val[ITER];
    int   off[ITER];
    float4 vj[ITER];
#pragma unroll
    for (int it = 0; it < ITER; ++it) {
        int idx = it * 8 + s;
        val[it] = (idx < KSEL);
        int j = sj[val[it] ? idx : 0];
        off[it] = j * (NI * NN) + q * 4;
        vj[it] = *reinterpret_cast<const float4*>(vglob + (b * NJ + j) * NN + q * 4);
        if (!val[it]) {
#pragma unroll
            for (int st = 0; st < 3; ++st)
                pipe[st][w][it][lane] = make_float4(0.f, 0.f, 0.f, 0.f);
        }
    }

    float4 acc[ITER];
#pragma unroll
    for (int it = 0; it < ITER; ++it) acc[it] = make_float4(0.f, 0.f, 0.f, 0.f);
    float entlog = 0.f;
    float cdacc  = 0.f;

#pragma unroll
    for (int p = 0; p < 2; ++p) {
        int i = i0 + w * 16 + p;
#pragma unroll
        for (int it = 0; it < ITER; ++it) {
            if (val[it]) {
                unsigned sa = (unsigned)__cvta_generic_to_shared(&pipe[p][w][it][lane]);
                CP_ASYNC16(sa, ub + off[it] + i * NN);
            }
        }
        CP_COMMIT();
    }

#pragma unroll
    for (int r = 0; r < 16; ++r) {
        if (r < 14) {
            int i = i0 + w * 16 + r + 2;
            int st = (r + 2) % 3;
#pragma unroll
            for (int it = 0; it < ITER; ++it) {
                if (val[it]) {
                    unsigned sa = (unsigned)__cvta_generic_to_shared(&pipe[st][w][it][lane]);
                    CP_ASYNC16(sa, ub + off[it] + i * NN);
                }
            }
            CP_COMMIT();
        } else {
            CP_COMMIT();
        }
        CP_WAIT2();

        int st = r % 3;
        float4 uu[ITER];
#pragma unroll
        for (int it = 0; it < ITER; ++it) uu[it] = pipe[st][w][it][lane];

        float e[ITER];
        float S = 0.f, CDloc = 0.f;
#pragma unroll
        for (int it = 0; it < ITER; ++it) {
            float dd = uu[it].x * vj[it].x + uu[it].y * vj[it].y
                     + uu[it].z * vj[it].z + uu[it].w * vj[it].w;
            dd += __shfl_xor_sync(0xFFFFFFFFu, dd, 1);
            dd += __shfl_xor_sync(0xFFFFFFFFu, dd, 2);
            e[it] = val[it] ? __expf(dd) : 0.f;
            S += e[it];
            if (val[it]) CDloc += e[it] * dd;
        }
        S += __shfl_xor_sync(0xFFFFFFFFu, S, 4);
        S += __shfl_xor_sync(0xFFFFFFFFu, S, 8);
        S += __shfl_xor_sync(0xFFFFFFFFu, S, 16);
        float inv = __fdividef(1.f, S);
        entlog += __logf(S);
        cdacc  += CDloc * inv;
#pragma unroll
        for (int it = 0; it < ITER; ++it) {
            float c = e[it] * inv;
            acc[it].x += c * uu[it].x;
            acc[it].y += c * uu[it].y;
            acc[it].z += c * uu[it].z;
            acc[it].w += c * uu[it].w;
        }
    }

    // finish entropy (deferred cross-lane reduce)
    cdacc += __shfl_xor_sync(0xFFFFFFFFu, cdacc, 4);
    cdacc += __shfl_xor_sync(0xFFFFFFFFu, cdacc, 8);
    cdacc += __shfl_xor_sync(0xFFFFFFFFu, cdacc, 16);
    float ent = entlog - cdacc;

#pragma unroll
    for (int it = 0; it < ITER; ++it) {
        if (val[it]) {
            int base = (it * 8 + s) * 16 + q * 4;
            *reinterpret_cast<float4*>(&ssum[w][base]) = acc[it];
        }
    }
    if (lane == 0) red[w] = ent;
    __syncthreads();
    for (int k = t; k < KSEL * 16; k += 256) {
        float v = 0.f;
#pragma unroll
        for (int ww = 0; ww < 8; ++ww) v += ssum[ww][k];
        int idx = k >> 4, n = k & 15;
        int j = sj[idx];
        g_S_part[(size_t)tb * (NB * NJ * NN) + (size_t)(b * NJ + j) * NN + n] = v;
    }
    if (t == 0) {
        float e = 0.f;
#pragma unroll
        for (int x = 0; x < 8; ++x) e += red[x];
        g_ent_part[ent_slot * (NTILES * NB) + tb * NB + b] = e;
    }
}

// =====================================================================
// squash from s partials (mask-aware; unselected capsules -> v = 0)
// =====================================================================
__device__ __forceinline__ float squash_elem(int gid, bool sel, const float* __restrict__ bias) {
    float s = 0.f;
    if (sel) {
#pragma unroll
        for (int tt = 0; tt < NTILES; ++tt) s += g_S_part[(size_t)tt * (NB * NJ * NN) + gid];
    }
    float ss = s;
#pragma unroll
    for (int o = 8; o; o >>= 1) ss += __shfl_xor_sync(0xFFFFFFFFu, ss, o);
    int n = gid & 15, j = (gid >> 4) & 31;
    float tb = (ss == 0.f) ? 0.f : (s + bias[j * NN + n]);
    float sq = tb * tb;
#pragma unroll
    for (int o = 8; o; o >>= 1) sq += __shfl_xor_sync(0xFFFFFFFFu, sq, o);
    return (sq == 0.f) ? 0.f : (sq / (1.f + sq)) * tb / sqrtf(sq + 1e-8f);
}

__global__ void __launch_bounds__(256) squash_mid_kernel(const float* __restrict__ bias) {
    int gid = blockIdx.x * 256 + threadIdx.x;
    int j = (gid >> 4) & 31, b = gid >> 9;
    bool sel = (g_mask1[b] >> j) & 1u;
    float v = squash_elem(gid, sel, bias);
    g_V1[gid] = v;
    g_VW[gid] = g_V0[gid] + v;
}

__global__ void __launch_bounds__(256) final_kernel(const float* __restrict__ bias,
                                                    float* __restrict__ out, int out_size) {
    int gid = blockIdx.x * 256 + threadIdx.x;
    int j = (gid >> 4) & 31, b = gid >> 9;
    bool sel = (g_mask2[b] >> j) & 1u;
    out[gid] = squash_elem(gid, sel, bias);
    if (blockIdx.x == 0 && threadIdx.x < NB && out_size >= NB * NJ * NN + NB * 3) {
        int bb = threadIdx.x;
        float e1 = 0.f, e2 = 0.f;
        for (int tt = 0; tt < NTILES; ++tt) {
            e1 += g_ent_part[0 * (NTILES * NB) + tt * NB + bb];
            e2 += g_ent_part[1 * (NTILES * NB) + tt * NB + bb];
        }
        float* eo = out + NB * NJ * NN;
        eo[bb * 3 + 0] = logf(32.0f);
        eo[bb * 3 + 1] = e1 * (1.f / (float)NI);
        eo[bb * 3 + 2] = e2 * (1.f / (float)NI);
    }
}

// =====================================================================
extern "C" void kernel_launch(void* const* d_in, const int* in_sizes, int n_in,
                              void* d_out, int out_size) {
    const float* u    = (const float*)d_in[0];
    const float* bias = (const float*)d_in[1];
    float* out        = (float*)d_out;

    float *v0p, *vwp;
    unsigned *m1p, *m2p;
    cudaGetSymbolAddress((void**)&v0p, g_V0);
    cudaGetSymbolAddress((void**)&vwp, g_VW);
    cudaGetSymbolAddress((void**)&m1p, g_mask1);
    cudaGetSymbolAddress((void**)&m2p, g_mask2);

    dim3 sgrid(NTILES, NB);

    // sweep 1 (302 MB): s0 -> v0
    pass1_kernel<<<dim3(NJ, NB), 256>>>(u, bias);
    // sweep 2 (302 MB): scores of softmax(u·v0) -> partials
    score_kernel<32><<<sgrid, 256>>>(u, v0p, nullptr);
    // sweep 3 (189 MB): top-20 mask (in-kernel), c1, entropy1, s1
    sum_kernel<20><<<sgrid, 256>>>(u, v0p, m1p, 0);
    // v1 = squash(s1), w = v0 + v1
    squash_mid_kernel<<<256, 256>>>(bias);
    // sweep 4 (189 MB): scores of softmax(u·w, mask1) -> partials
    score_kernel<20><<<sgrid, 256>>>(u, vwp, m1p);
    // sweep 5 (113 MB): top-12 mask (in-kernel), c2, entropy2, s2
    sum_kernel<12><<<sgrid, 256>>>(u, vwp, m2p, 1);
    // v2 -> out, entropies -> out
    final_kernel<<<256, 256>>>(bias, out, out_size);
}